// round 4
// baseline (speedup 1.0000x reference)
#include <cuda_runtime.h>

#define P_CONST 5.0f
#define A_CONST 10.0f
#define MAX_CLAUSES 1000000

// Scratch: interleaved (numerator, denominator) per clause + loss accumulator.
// Device globals are zero-initialized at load; loss_kernel restores the
// all-zero state after consuming it, so every graph replay starts clean.
__device__ float2 g_acc[MAX_CLAUSES];
__device__ double g_loss;
__device__ unsigned int g_done;

// ---------------------------------------------------------------------------
// Kernel 1: edge scatter, 4 pos + 4 neg edges per thread.
// Index rows loaded as int4 with streaming hint; (lit*w, w) accumulated with
// ONE float2 atomic (RED.64) per edge.
// ---------------------------------------------------------------------------
__device__ __forceinline__ void scatter_edge(const float* __restrict__ x,
                                             int c, int v, bool neg)
{
    float lit = __ldg(x + v);
    if (neg) lit = 1.0f - lit;
    float w = __expf(P_CONST * lit);
    atomicAdd(reinterpret_cast<float2*>(&g_acc[c]), make_float2(lit * w, w));
}

__global__ void __launch_bounds__(256) edge_kernel(
    const float* __restrict__ x,
    const int* __restrict__ adj_pos,   // [2, E]: row 0 = clause, row 1 = var
    const int* __restrict__ adj_neg,   // [2, E]
    int E4)                            // E/4
{
    int i = blockIdx.x * blockDim.x + threadIdx.x;
    if (i >= E4) return;

    const int E = E4 * 4;
    const int4* cp4 = reinterpret_cast<const int4*>(adj_pos);
    const int4* vp4 = reinterpret_cast<const int4*>(adj_pos + E);
    const int4* cn4 = reinterpret_cast<const int4*>(adj_neg);
    const int4* vn4 = reinterpret_cast<const int4*>(adj_neg + E);

    // streaming loads: indices are touched once, keep L1 for x gathers
    int4 cp = __ldcs(cp4 + i);
    int4 vp = __ldcs(vp4 + i);
    int4 cn = __ldcs(cn4 + i);
    int4 vn = __ldcs(vn4 + i);

    scatter_edge(x, cp.x, vp.x, false);
    scatter_edge(x, cp.y, vp.y, false);
    scatter_edge(x, cp.z, vp.z, false);
    scatter_edge(x, cp.w, vp.w, false);

    scatter_edge(x, cn.x, vn.x, true);
    scatter_edge(x, cn.y, vn.y, true);
    scatter_edge(x, cn.z, vn.z, true);
    scatter_edge(x, cn.w, vn.w, true);
}

// ---------------------------------------------------------------------------
// Kernel 2: per-clause sigmoid + squared error (2 clauses/thread, float4),
// block-reduced into g_loss, last block finalizes and resets all scratch
// state to zero for the next graph replay.
// ---------------------------------------------------------------------------
__global__ void __launch_bounds__(256) loss_kernel(
    const float* __restrict__ clause_count, int C2, float* out, float invC)
{
    float4* acc4 = reinterpret_cast<float4*>(g_acc);
    const float2* cc2 = reinterpret_cast<const float2*>(clause_count);
    const float4 z4 = make_float4(0.f, 0.f, 0.f, 0.f);

    float local = 0.0f;
    int stride = gridDim.x * blockDim.x;
    for (int i = blockIdx.x * blockDim.x + threadIdx.x; i < C2; i += stride) {
        float4 a = acc4[i];          // clauses 2i (x,y) and 2i+1 (z,w)
        float2 c = cc2[i];
        acc4[i] = z4;                // re-zero for next replay

        float m0 = a.x / a.y;
        float m1 = a.z / a.w;
        float s0 = 1.0f / (1.0f + __expf(-A_CONST * (m0 - 0.5f)));
        float s1 = 1.0f / (1.0f + __expf(-A_CONST * (m1 - 0.5f)));
        float d0 = s0 - c.x;
        float d1 = s1 - c.y;
        local += d0 * d0 + d1 * d1;
    }

    #pragma unroll
    for (int off = 16; off > 0; off >>= 1)
        local += __shfl_down_sync(0xffffffffu, local, off);

    __shared__ float warp_sums[8];
    __shared__ bool is_last;
    int lane = threadIdx.x & 31;
    int wid = threadIdx.x >> 5;
    if (lane == 0) warp_sums[wid] = local;
    __syncthreads();

    if (wid == 0) {
        float s = (lane < (blockDim.x >> 5)) ? warp_sums[lane] : 0.0f;
        #pragma unroll
        for (int off = 4; off > 0; off >>= 1)
            s += __shfl_down_sync(0xffffffffu, s, off);
        if (lane == 0) {
            atomicAdd(&g_loss, (double)s);
            __threadfence();
            unsigned int ticket = atomicAdd(&g_done, 1u);
            is_last = (ticket == gridDim.x - 1);
        }
    }
    __syncthreads();

    if (is_last && threadIdx.x == 0) {
        *out = (float)g_loss * invC;
        // reset scalars for the next replay
        g_loss = 0.0;
        __threadfence();
        g_done = 0u;
    }
}

// ---------------------------------------------------------------------------
// Launch
// Inputs (metadata order): xv f32 [V], adj_pos i32 [2*E], adj_neg i32 [2*E],
//                          clause_count f32 [C]. Output: f32 scalar loss.
// ---------------------------------------------------------------------------
extern "C" void kernel_launch(void* const* d_in, const int* in_sizes, int n_in,
                              void* d_out, int out_size)
{
    const float* xv = (const float*)d_in[0];
    const int*   ap = (const int*)d_in[1];
    const int*   an = (const int*)d_in[2];
    const float* cc = (const float*)d_in[3];
    float* out = (float*)d_out;

    int E = in_sizes[1] / 2;   // 3,000,000
    int C = in_sizes[3];       // 1,000,000
    int E4 = E / 4;

    const int T = 256;
    int edge_blocks = (E4 + T - 1) / T;
    edge_kernel<<<edge_blocks, T>>>(xv, ap, an, E4);

    loss_kernel<<<2048, T>>>(cc, C / 2, out, 1.0f / (float)C);
}